// round 8
// baseline (speedup 1.0000x reference)
#include <cuda_runtime.h>
#include <cuda_fp16.h>
#include <stdint.h>

#define G       512
#define CDIM    512
#define TILE_M  64
#define THREADS 256

// ---- SMEM layout (per CTA; 2 CTAs/SM) ----
#define SM_A       0                       // 64 x 1024B, XOR-swizzled
#define SM_BBASE   65536                   // 3 stages x (32 x 512B)
#define B_STAGE_SZ 16384
#define SM_QT      (SM_BBASE + 2 * B_STAGE_SZ)            // overlaid on stage 2
#define SM_CT      (SM_QT + 8192)
#define SM_PTS     (SM_BBASE + 3 * B_STAGE_SZ)
#define SM_TOTAL   (SM_PTS + 768)                         // 115456 (x2 = 230912)

// fp16 image of latents: [b][k][c] row-major
__device__ __align__(16) unsigned char g_Bprep[4ull * G * CDIM * 2];

__device__ __forceinline__ uint32_t cvta_s(const void* p) {
    return (uint32_t)__cvta_generic_to_shared(const_cast<void*>(p));
}

__device__ __forceinline__ uint32_t pack_h2(float lo, float hi) {
    __half2 h = __floats2half2_rn(lo, hi);
    return *reinterpret_cast<uint32_t*>(&h);
}

__device__ __forceinline__ void ldsm_x4(uint32_t addr, uint32_t* r) {
    asm volatile("ldmatrix.sync.aligned.m8n8.x4.shared.b16 {%0,%1,%2,%3}, [%4];"
                 : "=r"(r[0]), "=r"(r[1]), "=r"(r[2]), "=r"(r[3]) : "r"(addr));
}

__device__ __forceinline__ void ldsm_x4_t(uint32_t addr, uint32_t* r) {
    asm volatile("ldmatrix.sync.aligned.m8n8.x4.trans.shared.b16 {%0,%1,%2,%3}, [%4];"
                 : "=r"(r[0]), "=r"(r[1]), "=r"(r[2]), "=r"(r[3]) : "r"(addr));
}

__device__ __forceinline__ void mma16816(float* d, const uint32_t* a, const uint32_t* b) {
    asm volatile(
        "mma.sync.aligned.m16n8k16.row.col.f32.f16.f16.f32 "
        "{%0,%1,%2,%3}, {%4,%5,%6,%7}, {%8,%9}, {%0,%1,%2,%3};"
        : "+f"(d[0]), "+f"(d[1]), "+f"(d[2]), "+f"(d[3])
        : "r"(a[0]), "r"(a[1]), "r"(a[2]), "r"(a[3]), "r"(b[0]), "r"(b[1]));
}

// ---------- prep: elementwise fp32 -> fp16 convert of latents ----------
__global__ void rbf_prep(const float* __restrict__ lat) {
    int b = blockIdx.y;
    int i = blockIdx.x * blockDim.x + threadIdx.x;
    const float4* src = (const float4*)(lat + (size_t)b * G * CDIM);
    uint2* dst = (uint2*)(g_Bprep + (size_t)b * G * CDIM * 2);
    float4 v = src[i];
    uint2 o;
    o.x = pack_h2(v.x, v.y);
    o.y = pack_h2(v.z, v.w);
    dst[i] = o;
}

// ---------- main kernel ----------
__global__ void __launch_bounds__(THREADS, 2)
rbf_main(const float* __restrict__ points, const float* __restrict__ eps,
         float* __restrict__ out, int Ntot)
{
    extern __shared__ __align__(1024) unsigned char smem[];
    const uint32_t sbase = cvta_s(smem);
    const int tid  = threadIdx.x;
    const int wid  = tid >> 5;
    const int lane = tid & 31;
    const int b    = blockIdx.y;
    const int n0   = blockIdx.x * TILE_M;
    const unsigned char* Bsrc = g_Bprep + (size_t)b * (G * CDIM * 2);

    auto issue_slice = [&](int g) {
        int cc   = g >> 4;
        int kabs = (g & 15) * 32;
        uint32_t dstbase = sbase + SM_BBASE + (uint32_t)(g % 3) * B_STAGE_SZ;
        #pragma unroll
        for (int j = 0; j < 4; ++j) {
            int s  = tid + j * THREADS;
            int r  = s >> 5;
            int ch = s & 31;
            const unsigned char* src = Bsrc + ((size_t)(kabs + r) * CDIM + cc * 256) * 2 + ch * 16;
            uint32_t dst = dstbase + r * 512 + (uint32_t)((ch ^ (r & 7)) << 4);
            asm volatile("cp.async.cg.shared.global [%0], [%1], 16;" :: "r"(dst), "l"(src));
        }
        asm volatile("cp.async.commit_group;" ::: "memory");
    };

    issue_slice(0);
    issue_slice(1);

    // stage points
    {
        const float* psrc = points + ((size_t)b * Ntot + n0) * 3;
        int nfl = min(TILE_M, Ntot - n0) * 3;
        float* stage = (float*)(smem + SM_PTS);
        for (int i = tid; i < TILE_M * 3; i += THREADS)
            stage[i] = (i < nfl) ? psrc[i] : 0.0f;
    }

    // per-g tables (overlaid on stage-2 buffer; dead before slice 2 arrives)
    {
        float4* qt = (float4*)(smem + SM_QT);
        float*  ct = (float*)(smem + SM_CT);
        const float LOG2E = 1.4426950408889634f;
        const float step  = 2.0f / 7.0f;
        for (int g = tid; g < G; g += THREADS) {
            float gx = -1.0f + step * (float)(g >> 6);
            float gy = -1.0f + step * (float)((g >> 3) & 7);
            float gz = -1.0f + step * (float)(g & 7);
            float e  = eps[g];
            float s  = -e * e * LOG2E;
            qt[g] = make_float4(-2.0f * s * gx, -2.0f * s * gy, -2.0f * s * gz, s);
            ct[g] = s * (gx * gx + gy * gy + gz * gz);
        }
    }
    __syncthreads();

    // A-gen: thread -> (row = tid&63, kq = tid>>6), 128 exps -> swizzled fp16 SMEM
    {
        const int row   = tid & 63;
        const int kbase = (tid >> 6) * 128;
        const float* stage = (const float*)(smem + SM_PTS);
        float px = stage[row * 3 + 0], py = stage[row * 3 + 1], pz = stage[row * 3 + 2];
        float p2 = px * px + py * py + pz * pz;
        const float4* qt = (const float4*)(smem + SM_QT);
        const float*  ct = (const float*)(smem + SM_CT);
        const uint32_t arow = sbase + SM_A + (uint32_t)row * 1024;
        const int swz = row & 7;
        #pragma unroll 4
        for (int j = 0; j < 16; ++j) {
            float ev[8];
            #pragma unroll
            for (int q = 0; q < 8; ++q) {
                int g = kbase + j * 8 + q;
                float4 qv = qt[g];
                float arg = fmaf(qv.x, px, fmaf(qv.y, py,
                            fmaf(qv.z, pz, fmaf(qv.w, p2, ct[g]))));
                asm("ex2.approx.f32 %0, %1;" : "=f"(ev[q]) : "f"(arg));
            }
            uint4 pk;
            pk.x = pack_h2(ev[0], ev[1]);
            pk.y = pack_h2(ev[2], ev[3]);
            pk.z = pack_h2(ev[4], ev[5]);
            pk.w = pack_h2(ev[6], ev[7]);
            int cj = (kbase >> 3) + j;
            asm volatile("st.shared.v4.b32 [%0], {%1,%2,%3,%4};"
                         :: "r"(arow + (uint32_t)((cj ^ swz) << 4)),
                            "r"(pk.x), "r"(pk.y), "r"(pk.z), "r"(pk.w));
        }
    }
    __syncthreads();

    const int wm = (wid & 1) * 32;
    const int wn = (wid >> 1) * 64;
    const int hi = lane >> 4;              // 0/1

    // --- precomputed addressing (hoisted out of main loop) ---
    // A: addr = Abase[tm] + ((c ^ swzA[tm]) << 4), c = (g&15)*4 + kk*2 + hi
    uint32_t Abase[2], AswzX[2];
    #pragma unroll
    for (int tm = 0; tm < 2; ++tm) {
        int row = wm + tm * 16 + (lane & 15);
        Abase[tm] = sbase + SM_A + (uint32_t)row * 1024;
        AswzX[tm] = (uint32_t)(row & 7);
    }
    // B: addr = Bb + Boff[kk][tn2]  (rr, col fixed per kk,tn2)
    uint32_t Boff[2][4];
    #pragma unroll
    for (int kk = 0; kk < 2; ++kk)
        #pragma unroll
        for (int tn2 = 0; tn2 < 4; ++tn2) {
            int rr  = kk * 16 + (lane & 15);
            int colc = ((wn + tn2 * 16 + hi * 8) >> 3);
            Boff[kk][tn2] = (uint32_t)rr * 512 + (uint32_t)((colc ^ (rr & 7)) << 4);
        }

    float acc[2][8][4];
    #pragma unroll
    for (int tm = 0; tm < 2; ++tm)
        #pragma unroll
        for (int tn = 0; tn < 8; ++tn)
            #pragma unroll
            for (int q = 0; q < 4; ++q)
                acc[tm][tn][q] = 0.0f;

    for (int g = 0; g < 32; ++g) {
        asm volatile("cp.async.wait_group 1;" ::: "memory");
        __syncthreads();

        uint32_t Bb = sbase + SM_BBASE + (uint32_t)(g % 3) * B_STAGE_SZ;
        uint32_t c0 = (uint32_t)((g & 15) * 4 + hi);

        // load ALL fragments for both kk halves up front (rotating reg buffers)
        uint32_t af[2][2][4], bfr[2][4][4];
        #pragma unroll
        for (int kk = 0; kk < 2; ++kk) {
            #pragma unroll
            for (int tm = 0; tm < 2; ++tm)
                ldsm_x4(Abase[tm] + (((c0 + kk * 2) ^ AswzX[tm]) << 4), af[kk][tm]);
            #pragma unroll
            for (int tn2 = 0; tn2 < 4; ++tn2)
                ldsm_x4_t(Bb + Boff[kk][tn2], bfr[kk][tn2]);
        }

        // cp.async for g+2 issues under the MMA phase
        if (g + 2 < 32) issue_slice(g + 2);

        #pragma unroll
        for (int kk = 0; kk < 2; ++kk)
            #pragma unroll
            for (int tm = 0; tm < 2; ++tm)
                #pragma unroll
                for (int tn = 0; tn < 8; ++tn)
                    mma16816(acc[tm][tn], af[kk][tm], &bfr[kk][tn >> 1][(tn & 1) * 2]);

        if (g == 15 || g == 31) {
            int cc = g >> 4;
            #pragma unroll
            for (int tm = 0; tm < 2; ++tm) {
                int rbase = n0 + wm + tm * 16 + (lane >> 2);
                #pragma unroll
                for (int half = 0; half < 2; ++half) {
                    int r = rbase + half * 8;
                    if (r < Ntot) {
                        float* op = out + ((size_t)b * Ntot + r) * CDIM
                                    + cc * 256 + wn + (lane & 3) * 2;
                        #pragma unroll
                        for (int tn = 0; tn < 8; ++tn) {
                            float2 v = make_float2(acc[tm][tn][half * 2],
                                                   acc[tm][tn][half * 2 + 1]);
                            *reinterpret_cast<float2*>(op + tn * 8) = v;
                        }
                    }
                }
            }
            if (g == 15) {
                #pragma unroll
                for (int tm = 0; tm < 2; ++tm)
                    #pragma unroll
                    for (int tn = 0; tn < 8; ++tn)
                        #pragma unroll
                        for (int q = 0; q < 4; ++q)
                            acc[tm][tn][q] = 0.0f;
            }
        }
    }
}

extern "C" void kernel_launch(void* const* d_in, const int* in_sizes, int n_in,
                              void* d_out, int out_size) {
    const float* points = (const float*)d_in[0];
    const float* lat    = (const float*)d_in[1];
    const float* eps    = (const float*)d_in[2];
    float* out = (float*)d_out;

    int B = in_sizes[1] / (G * CDIM);          // 4
    int N = in_sizes[0] / (3 * B);             // 50000

    cudaFuncSetAttribute(rbf_main, cudaFuncAttributeMaxDynamicSharedMemorySize, SM_TOTAL);

    rbf_prep<<<dim3((G * CDIM / 4) / 256, B), 256>>>(lat);
    rbf_main<<<dim3((N + TILE_M - 1) / TILE_M, B), THREADS, SM_TOTAL>>>(points, eps, out, N);
}

// round 9
// speedup vs baseline: 1.2984x; 1.2984x over previous
#include <cuda_runtime.h>
#include <cuda_fp16.h>
#include <stdint.h>

#define G       512
#define CDIM    512
#define TILE_M  64
#define THREADS 256

// ---- SMEM layout (per CTA; 2 CTAs/SM) ----
#define SM_A       0                       // 64 x 1024B, XOR-swizzled
#define SM_BBASE   65536                   // 3 slots x (32 x 512B)
#define B_STAGE_SZ 16384
#define SM_QT      (SM_BBASE + 2 * B_STAGE_SZ)            // overlaid on slot 2
#define SM_CT      (SM_QT + 8192)
#define SM_PTS     (SM_BBASE + 3 * B_STAGE_SZ)            // 114688
#define SM_MBAR    (SM_PTS + 768)                         // 6 x 8B barriers
#define SM_TOTAL   (SM_MBAR + 64)                         // 115520 (x2 = 231040)

// fp16 image of latents: [b][k][c] row-major
__device__ __align__(16) unsigned char g_Bprep[4ull * G * CDIM * 2];

__device__ __forceinline__ uint32_t cvta_s(const void* p) {
    return (uint32_t)__cvta_generic_to_shared(const_cast<void*>(p));
}

__device__ __forceinline__ uint32_t pack_h2(float lo, float hi) {
    __half2 h = __floats2half2_rn(lo, hi);
    return *reinterpret_cast<uint32_t*>(&h);
}

__device__ __forceinline__ void ldsm_x4(uint32_t addr, uint32_t* r) {
    asm volatile("ldmatrix.sync.aligned.m8n8.x4.shared.b16 {%0,%1,%2,%3}, [%4];"
                 : "=r"(r[0]), "=r"(r[1]), "=r"(r[2]), "=r"(r[3]) : "r"(addr));
}

__device__ __forceinline__ void ldsm_x4_t(uint32_t addr, uint32_t* r) {
    asm volatile("ldmatrix.sync.aligned.m8n8.x4.trans.shared.b16 {%0,%1,%2,%3}, [%4];"
                 : "=r"(r[0]), "=r"(r[1]), "=r"(r[2]), "=r"(r[3]) : "r"(addr));
}

__device__ __forceinline__ void mma16816(float* d, const uint32_t* a, const uint32_t* b) {
    asm volatile(
        "mma.sync.aligned.m16n8k16.row.col.f32.f16.f16.f32 "
        "{%0,%1,%2,%3}, {%4,%5,%6,%7}, {%8,%9}, {%0,%1,%2,%3};"
        : "+f"(d[0]), "+f"(d[1]), "+f"(d[2]), "+f"(d[3])
        : "r"(a[0]), "r"(a[1]), "r"(a[2]), "r"(a[3]), "r"(b[0]), "r"(b[1]));
}

__device__ __forceinline__ void mbar_wait(uint32_t addr, uint32_t parity) {
    asm volatile(
        "{\n\t.reg .pred P;\n\t"
        "W_%=:\n\t"
        "mbarrier.try_wait.parity.acquire.cta.shared::cta.b64 P, [%0], %1, 0x989680;\n\t"
        "@!P bra W_%=;\n\t}"
        :: "r"(addr), "r"(parity) : "memory");
}

__device__ __forceinline__ void mbar_init(uint32_t addr, uint32_t cnt) {
    asm volatile("mbarrier.init.shared.b64 [%0], %1;" :: "r"(addr), "r"(cnt) : "memory");
}

__device__ __forceinline__ void mbar_arrive(uint32_t addr) {
    asm volatile("mbarrier.arrive.shared.b64 _, [%0];" :: "r"(addr) : "memory");
}

__device__ __forceinline__ void cpasync_arrive_noinc(uint32_t addr) {
    asm volatile("cp.async.mbarrier.arrive.noinc.shared::cta.b64 [%0];"
                 :: "r"(addr) : "memory");
}

// ---------- prep: elementwise fp32 -> fp16 convert of latents ----------
__global__ void rbf_prep(const float* __restrict__ lat) {
    int b = blockIdx.y;
    int i = blockIdx.x * blockDim.x + threadIdx.x;
    const float4* src = (const float4*)(lat + (size_t)b * G * CDIM);
    uint2* dst = (uint2*)(g_Bprep + (size_t)b * G * CDIM * 2);
    float4 v = src[i];
    uint2 o;
    o.x = pack_h2(v.x, v.y);
    o.y = pack_h2(v.z, v.w);
    dst[i] = o;
}

// ---------- main kernel ----------
__global__ void __launch_bounds__(THREADS, 2)
rbf_main(const float* __restrict__ points, const float* __restrict__ eps,
         float* __restrict__ out, int Ntot)
{
    extern __shared__ __align__(1024) unsigned char smem[];
    const uint32_t sbase = cvta_s(smem);
    const int tid  = threadIdx.x;
    const int wid  = tid >> 5;
    const int lane = tid & 31;
    const int b    = blockIdx.y;
    const int n0   = blockIdx.x * TILE_M;
    const unsigned char* Bsrc = g_Bprep + (size_t)b * (G * CDIM * 2);

    const uint32_t mb_full  = sbase + SM_MBAR;        // 3 x 8B
    const uint32_t mb_empty = sbase + SM_MBAR + 24;   // 3 x 8B

    if (tid == 0) {
        #pragma unroll
        for (int s = 0; s < 3; ++s) {
            mbar_init(mb_full + s * 8, THREADS);       // one cp.async-arrive per thread
            mbar_init(mb_empty + s * 8, 8);            // one arrive per warp
        }
    }
    __syncthreads();

    // issue cp.async for slice g into slot g%3 (each thread: 4 x 16B)
    auto issue_slice = [&](int g) {
        int cc   = g >> 4;
        int kabs = (g & 15) * 32;
        uint32_t dstbase = sbase + SM_BBASE + (uint32_t)(g % 3) * B_STAGE_SZ;
        #pragma unroll
        for (int j = 0; j < 4; ++j) {
            int s  = tid + j * THREADS;
            int r  = s >> 5;
            int ch = s & 31;
            const unsigned char* src = Bsrc + ((size_t)(kabs + r) * CDIM + cc * 256) * 2 + ch * 16;
            uint32_t dst = dstbase + r * 512 + (uint32_t)((ch ^ (r & 7)) << 4);
            asm volatile("cp.async.cg.shared.global [%0], [%1], 16;" :: "r"(dst), "l"(src));
        }
    };

    issue_slice(0); cpasync_arrive_noinc(mb_full + 0);
    issue_slice(1); cpasync_arrive_noinc(mb_full + 8);

    // stage points
    {
        const float* psrc = points + ((size_t)b * Ntot + n0) * 3;
        int nfl = min(TILE_M, Ntot - n0) * 3;
        float* stage = (float*)(smem + SM_PTS);
        for (int i = tid; i < TILE_M * 3; i += THREADS)
            stage[i] = (i < nfl) ? psrc[i] : 0.0f;
    }

    // per-g tables (overlaid on slot-2 buffer; dead before slice 2 is filled)
    {
        float4* qt = (float4*)(smem + SM_QT);
        float*  ct = (float*)(smem + SM_CT);
        const float LOG2E = 1.4426950408889634f;
        const float step  = 2.0f / 7.0f;
        for (int g = tid; g < G; g += THREADS) {
            float gx = -1.0f + step * (float)(g >> 6);
            float gy = -1.0f + step * (float)((g >> 3) & 7);
            float gz = -1.0f + step * (float)(g & 7);
            float e  = eps[g];
            float s  = -e * e * LOG2E;
            qt[g] = make_float4(-2.0f * s * gx, -2.0f * s * gy, -2.0f * s * gz, s);
            ct[g] = s * (gx * gx + gy * gy + gz * gz);
        }
    }
    __syncthreads();

    // A-gen: thread -> (row = tid&63, kq = tid>>6), 128 exps -> swizzled fp16 SMEM
    {
        const int row   = tid & 63;
        const int kbase = (tid >> 6) * 128;
        const float* stage = (const float*)(smem + SM_PTS);
        float px = stage[row * 3 + 0], py = stage[row * 3 + 1], pz = stage[row * 3 + 2];
        float p2 = px * px + py * py + pz * pz;
        const float4* qt = (const float4*)(smem + SM_QT);
        const float*  ct = (const float*)(smem + SM_CT);
        const uint32_t arow = sbase + SM_A + (uint32_t)row * 1024;
        const int swz = row & 7;
        #pragma unroll 4
        for (int j = 0; j < 16; ++j) {
            float ev[8];
            #pragma unroll
            for (int q = 0; q < 8; ++q) {
                int g = kbase + j * 8 + q;
                float4 qv = qt[g];
                float arg = fmaf(qv.x, px, fmaf(qv.y, py,
                            fmaf(qv.z, pz, fmaf(qv.w, p2, ct[g]))));
                asm("ex2.approx.f32 %0, %1;" : "=f"(ev[q]) : "f"(arg));
            }
            uint4 pk;
            pk.x = pack_h2(ev[0], ev[1]);
            pk.y = pack_h2(ev[2], ev[3]);
            pk.z = pack_h2(ev[4], ev[5]);
            pk.w = pack_h2(ev[6], ev[7]);
            int cj = (kbase >> 3) + j;
            asm volatile("st.shared.v4.b32 [%0], {%1,%2,%3,%4};"
                         :: "r"(arow + (uint32_t)((cj ^ swz) << 4)),
                            "r"(pk.x), "r"(pk.y), "r"(pk.z), "r"(pk.w));
        }
    }
    __syncthreads();                       // A visible; tables dead; slot-2 fill may begin

    const int wm = (wid & 1) * 32;
    const int wn = (wid >> 1) * 64;
    const int hi = lane >> 4;

    // hoisted addressing
    uint32_t Abase[2], AswzX[2];
    #pragma unroll
    for (int tm = 0; tm < 2; ++tm) {
        int row = wm + tm * 16 + (lane & 15);
        Abase[tm] = sbase + SM_A + (uint32_t)row * 1024;
        AswzX[tm] = (uint32_t)(row & 7);
    }
    uint32_t Boff[2][4];
    #pragma unroll
    for (int kk = 0; kk < 2; ++kk)
        #pragma unroll
        for (int tn2 = 0; tn2 < 4; ++tn2) {
            int rr   = kk * 16 + (lane & 15);
            int colc = (wn + tn2 * 16 + hi * 8) >> 3;
            Boff[kk][tn2] = (uint32_t)rr * 512 + (uint32_t)((colc ^ (rr & 7)) << 4);
        }

    float acc[2][8][4];
    #pragma unroll
    for (int tm = 0; tm < 2; ++tm)
        #pragma unroll
        for (int tn = 0; tn < 8; ++tn)
            #pragma unroll
            for (int q = 0; q < 4; ++q)
                acc[tm][tn][q] = 0.0f;

    for (int g = 0; g < 32; ++g) {
        const int slot = g % 3;
        mbar_wait(mb_full + slot * 8, (uint32_t)((g / 3) & 1));

        uint32_t Bb = sbase + SM_BBASE + (uint32_t)slot * B_STAGE_SZ;
        uint32_t c0 = (uint32_t)((g & 15) * 4 + hi);

        #pragma unroll
        for (int kk = 0; kk < 2; ++kk) {
            uint32_t af[2][4];
            #pragma unroll
            for (int tm = 0; tm < 2; ++tm)
                ldsm_x4(Abase[tm] + (((c0 + kk * 2) ^ AswzX[tm]) << 4), af[tm]);
            uint32_t bf[4][4];
            #pragma unroll
            for (int tn2 = 0; tn2 < 4; ++tn2)
                ldsm_x4_t(Bb + Boff[kk][tn2], bf[tn2]);
            #pragma unroll
            for (int tm = 0; tm < 2; ++tm)
                #pragma unroll
                for (int tn = 0; tn < 8; ++tn)
                    mma16816(acc[tm][tn], af[tm], &bf[tn >> 1][(tn & 1) * 2]);
        }

        if (lane == 0) mbar_arrive(mb_empty + slot * 8);     // slice g consumed (this warp)

        if (g + 2 < 32) {
            // slot (g+2)%3 was last used by slice g-1; wait until all warps freed it
            if (g >= 1)
                mbar_wait(mb_empty + ((g - 1) % 3) * 8, (uint32_t)(((g - 1) / 3) & 1));
            issue_slice(g + 2);
            cpasync_arrive_noinc(mb_full + ((g + 2) % 3) * 8);
        }

        if (g == 15 || g == 31) {
            int cc = g >> 4;
            #pragma unroll
            for (int tm = 0; tm < 2; ++tm) {
                int rbase = n0 + wm + tm * 16 + (lane >> 2);
                #pragma unroll
                for (int half = 0; half < 2; ++half) {
                    int r = rbase + half * 8;
                    if (r < Ntot) {
                        float* op = out + ((size_t)b * Ntot + r) * CDIM
                                    + cc * 256 + wn + (lane & 3) * 2;
                        #pragma unroll
                        for (int tn = 0; tn < 8; ++tn) {
                            float2 v = make_float2(acc[tm][tn][half * 2],
                                                   acc[tm][tn][half * 2 + 1]);
                            *reinterpret_cast<float2*>(op + tn * 8) = v;
                        }
                    }
                }
            }
            if (g == 15) {
                #pragma unroll
                for (int tm = 0; tm < 2; ++tm)
                    #pragma unroll
                    for (int tn = 0; tn < 8; ++tn)
                        #pragma unroll
                        for (int q = 0; q < 4; ++q)
                            acc[tm][tn][q] = 0.0f;
            }
        }
    }
}

extern "C" void kernel_launch(void* const* d_in, const int* in_sizes, int n_in,
                              void* d_out, int out_size) {
    const float* points = (const float*)d_in[0];
    const float* lat    = (const float*)d_in[1];
    const float* eps    = (const float*)d_in[2];
    float* out = (float*)d_out;

    int B = in_sizes[1] / (G * CDIM);          // 4
    int N = in_sizes[0] / (3 * B);             // 50000

    cudaFuncSetAttribute(rbf_main, cudaFuncAttributeMaxDynamicSharedMemorySize, SM_TOTAL);

    rbf_prep<<<dim3((G * CDIM / 4) / 256, B), 256>>>(lat);
    rbf_main<<<dim3((N + TILE_M - 1) / TILE_M, B), THREADS, SM_TOTAL>>>(points, eps, out, N);
}